// round 2
// baseline (speedup 1.0000x reference)
#include <cuda_runtime.h>
#include <cstdint>

#define BB 8
#define TT 12
#define NNODE 400
#define DD 128
#define HH 8
#define HDIM 16
#define UU 16
#define CC 64
#define FFD 2048
#define MROWS (BB*TT*NNODE)   /* 38400 */
#define BTN (BB*TT)           /* 96 */

// ---- single scratch arena (no allocations allowed) ----
// chunks of MROWS*DD floats: 0..12, then HID, KP, VP, SEN, ELIN, SENX, T400
#define CHSZ 4915200
#define OFF_HID   (13u*CHSZ)                     /* 63897600, size 78643200 */
#define OFF_KP    (OFF_HID + (size_t)MROWS*FFD)  /* 142540800 */
#define OFF_VP    (OFF_KP + (size_t)BTN*CC*DD)
#define OFF_SEN   (OFF_VP + (size_t)BTN*CC*DD)
#define OFF_ELIN  (OFF_SEN + (size_t)NNODE*DD)
#define OFF_SENX  (OFF_ELIN + (size_t)NNODE*DD)
#define OFF_T400  (OFF_SENX + (size_t)NNODE*DD)
#define SCRATCH_TOTAL (OFF_T400 + (size_t)NNODE*DD)

__device__ float g_scratch[SCRATCH_TOTAL];

// ---------------- generic SGEMM: C = act(A[MxK] @ W[KxN] + bias) ----------
__global__ __launch_bounds__(256) void sgemm_kernel(
    const float* __restrict__ A, const float* __restrict__ W,
    const float* __restrict__ bias, float* __restrict__ C,
    int M, int N, int K, int relu)
{
    __shared__ float As[16][64];
    __shared__ float Bs[16][128];
    int tid = threadIdx.x;
    int tx = tid & 15, ty = tid >> 4;
    int m0 = blockIdx.x * 64;
    int n0 = blockIdx.y * 128;
    int arow = tid >> 2;
    int akq  = (tid & 3) << 2;
    int bk   = tid >> 4;
    int bc   = (tid & 15) << 3;

    float acc[4][8];
#pragma unroll
    for (int i = 0; i < 4; i++)
#pragma unroll
        for (int j = 0; j < 8; j++) acc[i][j] = 0.f;

    for (int kk = 0; kk < K; kk += 16) {
        float4 av = make_float4(0.f, 0.f, 0.f, 0.f);
        if (m0 + arow < M)
            av = *(const float4*)&A[(size_t)(m0 + arow) * K + kk + akq];
        As[akq + 0][arow] = av.x;
        As[akq + 1][arow] = av.y;
        As[akq + 2][arow] = av.z;
        As[akq + 3][arow] = av.w;

        float4 b0 = *(const float4*)&W[(size_t)(kk + bk) * N + n0 + bc];
        float4 b1 = *(const float4*)&W[(size_t)(kk + bk) * N + n0 + bc + 4];
        *(float4*)&Bs[bk][bc]     = b0;
        *(float4*)&Bs[bk][bc + 4] = b1;
        __syncthreads();

#pragma unroll
        for (int k = 0; k < 16; k++) {
            float4 a4  = *(const float4*)&As[k][ty * 4];
            float4 bb0 = *(const float4*)&Bs[k][tx * 8];
            float4 bb1 = *(const float4*)&Bs[k][tx * 8 + 4];
            float a[4] = {a4.x, a4.y, a4.z, a4.w};
            float b[8] = {bb0.x, bb0.y, bb0.z, bb0.w, bb1.x, bb1.y, bb1.z, bb1.w};
#pragma unroll
            for (int i = 0; i < 4; i++)
#pragma unroll
                for (int j = 0; j < 8; j++)
                    acc[i][j] = fmaf(a[i], b[j], acc[i][j]);
        }
        __syncthreads();
    }

    float bv[8];
#pragma unroll
    for (int j = 0; j < 8; j++) bv[j] = bias[n0 + tx * 8 + j];
#pragma unroll
    for (int i = 0; i < 4; i++) {
        int r = m0 + ty * 4 + i;
        if (r < M) {
            float o[8];
#pragma unroll
            for (int j = 0; j < 8; j++) {
                float v = acc[i][j] + bv[j];
                o[j] = relu ? fmaxf(v, 0.f) : v;
            }
            *(float4*)&C[(size_t)r * N + n0 + tx * 8]     = make_float4(o[0], o[1], o[2], o[3]);
            *(float4*)&C[(size_t)r * N + n0 + tx * 8 + 4] = make_float4(o[4], o[5], o[6], o[7]);
        }
    }
}

// ---------------- LayerNorm family (128 threads = one row) ----------------
__device__ __forceinline__ float block_sum_128(float v, float* sb) {
#pragma unroll
    for (int o = 16; o; o >>= 1) v += __shfl_xor_sync(0xffffffffu, v, o);
    if ((threadIdx.x & 31) == 0) sb[threadIdx.x >> 5] = v;
    __syncthreads();
    float r = sb[0] + sb[1] + sb[2] + sb[3];
    __syncthreads();
    return r;
}

__global__ void ln_kernel(const float* __restrict__ in, const float* __restrict__ g,
                          const float* __restrict__ b, float* __restrict__ outp)
{
    __shared__ float sb[4];
    int t = threadIdx.x;
    size_t i = (size_t)blockIdx.x * 128 + t;
    float v = in[i];
    float mean = block_sum_128(v, sb) * (1.f / 128.f);
    float d = v - mean;
    float var = block_sum_128(d * d, sb) * (1.f / 128.f);
    outp[i] = d * rsqrtf(var + 1e-5f) * g[t] + b[t];
}

__global__ void lnsum4_kernel(const float* __restrict__ x, const float* __restrict__ a,
                              const float* __restrict__ bp, const float* __restrict__ c,
                              const float* __restrict__ g, const float* __restrict__ be,
                              float* __restrict__ outp)
{
    __shared__ float sb[4];
    int t = threadIdx.x;
    size_t i = (size_t)blockIdx.x * 128 + t;
    float v = x[i] + a[i] + bp[i] + c[i];
    float mean = block_sum_128(v, sb) * (1.f / 128.f);
    float d = v - mean;
    float var = block_sum_128(d * d, sb) * (1.f / 128.f);
    outp[i] = d * rsqrtf(var + 1e-5f) * g[t] + be[t];
}

__global__ void ln2mul_kernel(const float* __restrict__ f, const float* __restrict__ s,
                              const float* __restrict__ senx,
                              const float* __restrict__ g, const float* __restrict__ be,
                              float* __restrict__ attn2, float* __restrict__ spin)
{
    __shared__ float sb[4];
    int t = threadIdx.x;
    int r = blockIdx.x;
    size_t i = (size_t)r * 128 + t;
    float v = f[i] + s[i];
    float mean = block_sum_128(v, sb) * (1.f / 128.f);
    float d = v - mean;
    float var = block_sum_128(d * d, sb) * (1.f / 128.f);
    float o = d * rsqrtf(var + 1e-5f) * g[t] + be[t];
    attn2[i] = o;
    spin[i]  = o * senx[(size_t)(r % NNODE) * 128 + t];
}

__global__ void final_kernel(const float* __restrict__ f2, const float* __restrict__ attn2,
                             const float* __restrict__ g, const float* __restrict__ be,
                             float* __restrict__ outp)
{
    __shared__ float sb[4];
    int t = threadIdx.x;
    size_t i = (size_t)blockIdx.x * 128 + t;
    float v = f2[i];
    float mean = block_sum_128(v, sb) * (1.f / 128.f);
    float d = v - mean;
    float var = block_sum_128(d * d, sb) * (1.f / 128.f);
    float sp = d * rsqrtf(var + 1e-5f) * g[t] + be[t];
    outp[i] = attn2[i] + sp;
}

// ---------------- adaptive avg pool over node axis -------------------------
__global__ void pool_kernel(const float* __restrict__ Kin, const float* __restrict__ Vin,
                            float* __restrict__ Kp, float* __restrict__ Vp)
{
    int bt = blockIdx.x, c = blockIdx.y, d = threadIdx.x;
    int s = (c * NNODE) / CC;
    int e = ((c + 1) * NNODE + CC - 1) / CC;
    float inv = 1.f / (float)(e - s);
    float ak = 0.f, av = 0.f;
    for (int n = s; n < e; n++) {
        ak += Kin[((size_t)bt * NNODE + n) * DD + d];
        av += Vin[((size_t)bt * NNODE + n) * DD + d];
    }
    Kp[((size_t)bt * CC + c) * DD + d] = ak * inv;
    Vp[((size_t)bt * CC + c) * DD + d] = av * inv;
}

// ---------------- dtw attention: 400 keys, block = (bt, head) --------------
__global__ __launch_bounds__(256) void attn_dtw_kernel(
    const float* __restrict__ Q, const float* __restrict__ K,
    const float* __restrict__ V, float* __restrict__ O)
{
    extern __shared__ float sm[];
    float* Qs = sm;               // 400*16
    float* Kt = sm + 6400;        // 16*416
    float* Vt = sm + 6400 + 6656;
    int bt = blockIdx.x, h = blockIdx.y;
    size_t base = ((size_t)bt * NNODE) * DD + h * HDIM;
    int tid = threadIdx.x;
    for (int e = tid; e < NNODE * 4; e += 256) {
        int q = e >> 2, d4 = (e & 3) << 2;
        float4 qv = *(const float4*)&Q[base + (size_t)q * DD + d4];
        float4 kv = *(const float4*)&K[base + (size_t)q * DD + d4];
        float4 vv = *(const float4*)&V[base + (size_t)q * DD + d4];
        *(float4*)&Qs[q * 16 + d4] = qv;
        Kt[(d4 + 0) * 416 + q] = kv.x; Kt[(d4 + 1) * 416 + q] = kv.y;
        Kt[(d4 + 2) * 416 + q] = kv.z; Kt[(d4 + 3) * 416 + q] = kv.w;
        Vt[(d4 + 0) * 416 + q] = vv.x; Vt[(d4 + 1) * 416 + q] = vv.y;
        Vt[(d4 + 2) * 416 + q] = vv.z; Vt[(d4 + 3) * 416 + q] = vv.w;
    }
    __syncthreads();
    int warp = tid >> 5, lane = tid & 31;
    for (int pp = warp; pp < NNODE / 2; pp += 8) {
        int qa = pp * 2;
        float qva[16], qvb[16];
#pragma unroll
        for (int d = 0; d < 16; d++) {
            qva[d] = Qs[qa * 16 + d];
            qvb[d] = Qs[qa * 16 + 16 + d];
        }
        float sa[13], sbv[13];
        float mxa = -1e30f, mxb = -1e30f;
#pragma unroll
        for (int i = 0; i < 13; i++) {
            int j = lane + (i << 5);
            float s0 = -1e30f, s1 = -1e30f;
            if (j < NNODE) {
                s0 = 0.f; s1 = 0.f;
#pragma unroll
                for (int d = 0; d < 16; d++) {
                    float kv = Kt[d * 416 + j];
                    s0 = fmaf(qva[d], kv, s0);
                    s1 = fmaf(qvb[d], kv, s1);
                }
                s0 *= 0.25f; s1 *= 0.25f;
            }
            sa[i] = s0; sbv[i] = s1;
            mxa = fmaxf(mxa, s0); mxb = fmaxf(mxb, s1);
        }
#pragma unroll
        for (int o = 16; o; o >>= 1) {
            mxa = fmaxf(mxa, __shfl_xor_sync(0xffffffffu, mxa, o));
            mxb = fmaxf(mxb, __shfl_xor_sync(0xffffffffu, mxb, o));
        }
        float la = 0.f, lb = 0.f;
#pragma unroll
        for (int i = 0; i < 13; i++) {
            int j = lane + (i << 5);
            float pa = (j < NNODE) ? __expf(sa[i] - mxa) : 0.f;
            float pb = (j < NNODE) ? __expf(sbv[i] - mxb) : 0.f;
            sa[i] = pa; sbv[i] = pb;
            la += pa; lb += pb;
        }
#pragma unroll
        for (int o = 16; o; o >>= 1) {
            la += __shfl_xor_sync(0xffffffffu, la, o);
            lb += __shfl_xor_sync(0xffffffffu, lb, o);
        }
        float acca[16], accb[16];
#pragma unroll
        for (int d = 0; d < 16; d++) { acca[d] = 0.f; accb[d] = 0.f; }
#pragma unroll
        for (int i = 0; i < 13; i++) {
            int j = lane + (i << 5);
            if (j < NNODE) {
                float pa = sa[i], pb = sbv[i];
#pragma unroll
                for (int d = 0; d < 16; d++) {
                    float vv = Vt[d * 416 + j];
                    acca[d] = fmaf(pa, vv, acca[d]);
                    accb[d] = fmaf(pb, vv, accb[d]);
                }
            }
        }
#pragma unroll
        for (int d = 0; d < 16; d++) {
#pragma unroll
            for (int o = 16; o; o >>= 1) {
                acca[d] += __shfl_xor_sync(0xffffffffu, acca[d], o);
                accb[d] += __shfl_xor_sync(0xffffffffu, accb[d], o);
            }
        }
        if (lane < 16) {
            O[base + (size_t)qa * DD + lane]       = acca[lane] / la;
            O[base + (size_t)(qa + 1) * DD + lane] = accb[lane] / lb;
        }
    }
}

// ---------------- pooled attention: 64 keys + positional bias --------------
__global__ __launch_bounds__(256) void attn_adp_kernel(
    const float* __restrict__ Q, const float* __restrict__ Kp,
    const float* __restrict__ Vp, const float* __restrict__ pos,
    float* __restrict__ O)
{
    __shared__ float Qs[NNODE * 16];
    __shared__ float Kt[16 * 64];
    __shared__ float Vt[16 * 64];
    int bt = blockIdx.x, h = blockIdx.y, tid = threadIdx.x;
    size_t qbase = ((size_t)bt * NNODE) * DD + h * HDIM;
    size_t kbase = ((size_t)bt * CC) * DD + h * HDIM;
    for (int e = tid; e < NNODE * 4; e += 256) {
        int q = e >> 2, d4 = (e & 3) << 2;
        *(float4*)&Qs[q * 16 + d4] = *(const float4*)&Q[qbase + (size_t)q * DD + d4];
    }
    {
        int c = tid >> 2, d4 = (tid & 3) << 2;
        float4 kv = *(const float4*)&Kp[kbase + (size_t)c * DD + d4];
        float4 vv = *(const float4*)&Vp[kbase + (size_t)c * DD + d4];
        Kt[(d4 + 0) * 64 + c] = kv.x; Kt[(d4 + 1) * 64 + c] = kv.y;
        Kt[(d4 + 2) * 64 + c] = kv.z; Kt[(d4 + 3) * 64 + c] = kv.w;
        Vt[(d4 + 0) * 64 + c] = vv.x; Vt[(d4 + 1) * 64 + c] = vv.y;
        Vt[(d4 + 2) * 64 + c] = vv.z; Vt[(d4 + 3) * 64 + c] = vv.w;
    }
    __syncthreads();
    int warp = tid >> 5, lane = tid & 31;
    for (int pp = warp; pp < NNODE / 2; pp += 8) {
        int qa = pp * 2;
        float qva[16], qvb[16];
#pragma unroll
        for (int d = 0; d < 16; d++) {
            qva[d] = Qs[qa * 16 + d];
            qvb[d] = Qs[qa * 16 + 16 + d];
        }
        float s00 = 0.f, s01 = 0.f, s10 = 0.f, s11 = 0.f;
#pragma unroll
        for (int d = 0; d < 16; d++) {
            float k0 = Kt[d * 64 + lane], k1 = Kt[d * 64 + lane + 32];
            s00 = fmaf(qva[d], k0, s00); s01 = fmaf(qva[d], k1, s01);
            s10 = fmaf(qvb[d], k0, s10); s11 = fmaf(qvb[d], k1, s11);
        }
        s00 = s00 * 0.25f + pos[(size_t)qa * 64 + lane];
        s01 = s01 * 0.25f + pos[(size_t)qa * 64 + lane + 32];
        s10 = s10 * 0.25f + pos[(size_t)(qa + 1) * 64 + lane];
        s11 = s11 * 0.25f + pos[(size_t)(qa + 1) * 64 + lane + 32];
        float mxa = fmaxf(s00, s01), mxb = fmaxf(s10, s11);
#pragma unroll
        for (int o = 16; o; o >>= 1) {
            mxa = fmaxf(mxa, __shfl_xor_sync(0xffffffffu, mxa, o));
            mxb = fmaxf(mxb, __shfl_xor_sync(0xffffffffu, mxb, o));
        }
        float p00 = __expf(s00 - mxa), p01 = __expf(s01 - mxa);
        float p10 = __expf(s10 - mxb), p11 = __expf(s11 - mxb);
        float la = p00 + p01, lb = p10 + p11;
#pragma unroll
        for (int o = 16; o; o >>= 1) {
            la += __shfl_xor_sync(0xffffffffu, la, o);
            lb += __shfl_xor_sync(0xffffffffu, lb, o);
        }
        float acca[16], accb[16];
#pragma unroll
        for (int d = 0; d < 16; d++) {
            float v0 = Vt[d * 64 + lane], v1 = Vt[d * 64 + lane + 32];
            acca[d] = p00 * v0 + p01 * v1;
            accb[d] = p10 * v0 + p11 * v1;
        }
#pragma unroll
        for (int d = 0; d < 16; d++) {
#pragma unroll
            for (int o = 16; o; o >>= 1) {
                acca[d] += __shfl_xor_sync(0xffffffffu, acca[d], o);
                accb[d] += __shfl_xor_sync(0xffffffffu, accb[d], o);
            }
        }
        if (lane < 16) {
            O[qbase + (size_t)qa * DD + lane]       = acca[lane] / la;
            O[qbase + (size_t)(qa + 1) * DD + lane] = accb[lane] / lb;
        }
    }
}

// ---------------- GEANet edge path (sen -> sen_extra) ----------------------
__global__ void edge_kernel(const float* __restrict__ elin, const float* __restrict__ ew,
                            const float* __restrict__ eb, float* __restrict__ senx,
                            float* __restrict__ outtail)
{
    __shared__ float s0[128], s1[128], s2[128];
    int n = blockIdx.x, t = threadIdx.x;
    int h = t >> 4, u = t & 15;
    s0[t] = elin[(size_t)n * 128 + t];
    __syncthreads();
    float acc = eb[u];
#pragma unroll
    for (int k = 0; k < 16; k++) acc = fmaf(s0[k * 8 + h], ew[k * 16 + u], acc);
    s1[t] = acc;
    __syncthreads();
    float mx = -1e30f;
#pragma unroll
    for (int hh = 0; hh < 8; hh++) mx = fmaxf(mx, s1[hh * 16 + u]);
    float sume = 0.f;
#pragma unroll
    for (int hh = 0; hh < 8; hh++) sume += __expf(s1[hh * 16 + u] - mx);
    float a = __expf(acc - mx) / sume;
    s2[t] = a;
    __syncthreads();
    float rs = 0.f;
#pragma unroll
    for (int uu = 0; uu < 16; uu++) rs += s2[h * 16 + uu];
    float a2 = a / rs;
    __syncthreads();
    s0[t] = a2;
    __syncthreads();
    float y = eb[16 + u];
#pragma unroll
    for (int k = 0; k < 16; k++) y = fmaf(s0[h * 16 + k], ew[256 + k * 16 + u], y);
    senx[(size_t)n * 128 + t] = y;
    outtail[(size_t)n * 128 + t] = y;
}

// ---------------- GEANet node path (reshape-of-transpose perm) -------------
__global__ void node_kernel(const float* __restrict__ share, const float* __restrict__ nw,
                            const float* __restrict__ nb, float* __restrict__ extra)
{
    __shared__ float s0[128], s1[128], s2[128];
    int row = blockIdx.x;
    int b = row / (TT * NNODE), p = row % (TT * NNODE);
    int nn = p / TT, ll = p % TT;
    int t = threadIdx.x;
    int h = t >> 4, u = t & 15;
    s0[t] = share[(((size_t)b * TT + ll) * NNODE + nn) * 128 + t];
    __syncthreads();
    float acc = nb[u];
#pragma unroll
    for (int k = 0; k < 16; k++) acc = fmaf(s0[h * 16 + k], nw[k * 16 + u], acc);
    s1[t] = acc;
    __syncthreads();
    float mx = -1e30f;
#pragma unroll
    for (int hh = 0; hh < 8; hh++) mx = fmaxf(mx, s1[hh * 16 + u]);
    float sume = 0.f;
#pragma unroll
    for (int hh = 0; hh < 8; hh++) sume += __expf(s1[hh * 16 + u] - mx);
    float a = __expf(acc - mx) / sume;
    s2[t] = a;
    __syncthreads();
    float rs = 0.f;
#pragma unroll
    for (int uu = 0; uu < 16; uu++) rs += s2[h * 16 + uu];
    float a2 = a / rs;
    __syncthreads();
    s0[t] = a2;
    __syncthreads();
    float y = nb[16 + u];
#pragma unroll
    for (int k = 0; k < 16; k++) y = fmaf(s0[h * 16 + k], nw[256 + k * 16 + u], y);
    extra[(size_t)row * 128 + t] = y;
}

// ---------------- host orchestration ---------------------------------------
extern "C" void kernel_launch(void* const* d_in, const int* in_sizes, int n_in,
                              void* d_out, int out_size)
{
    const float* x         = (const float*)d_in[0];
    const float* spe       = (const float*)d_in[1];
    const float* dtw_qkv_w = (const float*)d_in[2];
    const float* dtw_qkv_b = (const float*)d_in[3];
    const float* dtw_out_w = (const float*)d_in[4];
    const float* dtw_out_b = (const float*)d_in[5];
    const float* att_qkv_w = (const float*)d_in[6];
    const float* att_qkv_b = (const float*)d_in[7];
    const float* att_out_w = (const float*)d_in[8];
    const float* att_out_b = (const float*)d_in[9];
    const float* adp_pos   = (const float*)d_in[10];
    const float* share_w   = (const float*)d_in[11];
    const float* share_b   = (const float*)d_in[12];
    const float* node_w    = (const float*)d_in[13];
    const float* node_b    = (const float*)d_in[14];
    const float* edge_w    = (const float*)d_in[15];
    const float* edge_b    = (const float*)d_in[16];
    const float* spatial_w = (const float*)d_in[17];
    const float* spatial_b = (const float*)d_in[18];
    const float* ff1w1     = (const float*)d_in[19];
    const float* ff1b1     = (const float*)d_in[20];
    const float* ff1w2     = (const float*)d_in[21];
    const float* ff1b2     = (const float*)d_in[22];
    const float* ff2w1     = (const float*)d_in[23];
    const float* ff2b1     = (const float*)d_in[24];
    const float* ff2w2     = (const float*)d_in[25];
    const float* ff2b2     = (const float*)d_in[26];
    const float* lns       = (const float*)d_in[27];
    const float* lnb       = (const float*)d_in[28];
    float* out = (float*)d_out;

    float* g = nullptr;
    { void* p; cudaGetSymbolAddress(&p, g_scratch); g = (float*)p; }
    float* Q1   = g + 0u * CHSZ;
    float* K1   = g + 1u * CHSZ;
    float* V1   = g + 2u * CHSZ;
    float* Q2   = g + 3u * CHSZ;
    float* K2   = g + 4u * CHSZ;
    float* V2   = g + 5u * CHSZ;
    float* SHR  = g + 6u * CHSZ;
    float* DTW  = g + 7u * CHSZ;
    float* OA   = g + 8u * CHSZ;
    float* B1   = g + 9u * CHSZ;
    float* B2   = g + 10u * CHSZ;
    float* B3   = g + 11u * CHSZ;
    float* B4   = g + 12u * CHSZ;
    float* HID  = g + OFF_HID;
    float* KP   = g + OFF_KP;
    float* VP   = g + OFF_VP;
    float* SEN  = g + OFF_SEN;
    float* ELIN = g + OFF_ELIN;
    float* SENX = g + OFF_SENX;
    float* T400 = g + OFF_T400;

    static int smem_set = 0;
    if (!smem_set) {
        cudaFuncSetAttribute(attn_dtw_kernel,
                             cudaFuncAttributeMaxDynamicSharedMemorySize, 78848);
        smem_set = 1;
    }

#define GEMM(A_, W_, Bi_, C_, M_, N_, K_, R_) \
    sgemm_kernel<<<dim3(((M_) + 63) / 64, (N_) / 128), 256>>>(A_, W_, Bi_, C_, M_, N_, K_, R_)

    // sen path: sen = LN(spe @ spatial_w + b), elin = sen @ share_w + b, edge
    GEMM(spe, spatial_w, spatial_b, T400, NNODE, DD, DD, 0);
    ln_kernel<<<NNODE, 128>>>(T400, lns + 3 * 128, lnb + 3 * 128, SEN);
    GEMM(SEN, share_w, share_b, ELIN, NNODE, DD, DD, 0);
    edge_kernel<<<NNODE, 128>>>(ELIN, edge_w, edge_b, SENX, out + (size_t)MROWS * DD);

    // QKV projections (dtw + pooled attention), GEANet share
    GEMM(x, dtw_qkv_w + 0 * DD * DD, dtw_qkv_b + 0 * DD, Q1, MROWS, DD, DD, 0);
    GEMM(x, dtw_qkv_w + 1 * DD * DD, dtw_qkv_b + 1 * DD, K1, MROWS, DD, DD, 0);
    GEMM(x, dtw_qkv_w + 2 * DD * DD, dtw_qkv_b + 2 * DD, V1, MROWS, DD, DD, 0);
    GEMM(x, att_qkv_w + 0 * DD * DD, att_qkv_b + 0 * DD, Q2, MROWS, DD, DD, 0);
    GEMM(x, att_qkv_w + 1 * DD * DD, att_qkv_b + 1 * DD, K2, MROWS, DD, DD, 0);
    GEMM(x, att_qkv_w + 2 * DD * DD, att_qkv_b + 2 * DD, V2, MROWS, DD, DD, 0);
    GEMM(x, share_w, share_b, SHR, MROWS, DD, DD, 0);

    // GEANet node path
    node_kernel<<<MROWS, 128>>>(SHR, node_w, node_b, B1);

    // dtw attention + out projection
    attn_dtw_kernel<<<dim3(BTN, HH), 256, 78848>>>(Q1, K1, V1, B2);
    GEMM(B2, dtw_out_w, dtw_out_b, DTW, MROWS, DD, DD, 0);

    // pooled attention + out projection
    pool_kernel<<<dim3(BTN, CC), 128>>>(K2, V2, KP, VP);
    attn_adp_kernel<<<dim3(BTN, HH), 256>>>(Q2, KP, VP, adp_pos, B2);
    GEMM(B2, att_out_w, att_out_b, OA, MROWS, DD, DD, 0);

    // ln1 of (x + oa + dtw + extra)
    lnsum4_kernel<<<MROWS, 128>>>(x, OA, DTW, B1, lns + 0, lnb + 0, B4);

    // feed_forward1 + ln2, fused with sen_extra multiply
    GEMM(B4, ff1w1, ff1b1, HID, MROWS, FFD, DD, 1);
    GEMM(HID, ff1w2, ff1b2, B1, MROWS, DD, FFD, 0);
    ln2mul_kernel<<<MROWS, 128>>>(B1, B4, SENX, lns + 128, lnb + 128, B2, B3);

    // feed_forward2 + spatial_norm + residual
    GEMM(B3, ff2w1, ff2b1, HID, MROWS, FFD, DD, 1);
    GEMM(HID, ff2w2, ff2b2, B4, MROWS, DD, FFD, 0);
    final_kernel<<<MROWS, 128>>>(B4, B2, lns + 2 * 128, lnb + 2 * 128, out);
#undef GEMM
}

// round 3
// speedup vs baseline: 1.4885x; 1.4885x over previous
#include <cuda_runtime.h>
#include <cstdint>

#define BB 8
#define TT 12
#define NNODE 400
#define DD 128
#define HH 8
#define HDIM 16
#define UU 16
#define CC 64
#define FFD 2048
#define MROWS (BB*TT*NNODE)   /* 38400 */
#define BTN (BB*TT)           /* 96 */

// ---- single scratch arena (no allocations allowed) ----
#define CHSZ 4915200
#define OFF_HID   (13u*CHSZ)
#define OFF_KP    (OFF_HID + (size_t)MROWS*FFD)
#define OFF_VP    (OFF_KP + (size_t)BTN*CC*DD)
#define OFF_SEN   (OFF_VP + (size_t)BTN*CC*DD)
#define OFF_ELIN  (OFF_SEN + (size_t)NNODE*DD)
#define OFF_SENX  (OFF_ELIN + (size_t)NNODE*DD)
#define OFF_T400  (OFF_SENX + (size_t)NNODE*DD)
#define SCRATCH_TOTAL (OFF_T400 + (size_t)NNODE*DD)

__device__ float g_scratch[SCRATCH_TOTAL];
__device__ float g_zerobias[FFD];   // static zero-init

// ---------------- f32x2 helpers --------------------------------------------
__device__ __forceinline__ void fma2(unsigned long long& d,
                                     unsigned long long a, unsigned long long b) {
    asm("fma.rn.f32x2 %0, %1, %2, %0;" : "+l"(d) : "l"(a), "l"(b));
}
__device__ __forceinline__ unsigned long long bcast2(float x) {
    unsigned long long r;
    unsigned int xi = __float_as_uint(x);
    asm("mov.b64 %0, {%1, %1};" : "=l"(r) : "r"(xi));
    return r;
}
__device__ __forceinline__ float2 unpack2(unsigned long long v) {
    unsigned int lo, hi;
    asm("mov.b64 {%0, %1}, %2;" : "=r"(lo), "=r"(hi) : "l"(v));
    return make_float2(__uint_as_float(lo), __uint_as_float(hi));
}

// ---------------- 128x128-tile f32x2 SGEMM ---------------------------------
// C[M,N] = act(A[M,lda(cols)] (cols kk0..kk0+K) @ W[K,N] + bias)
__global__ __launch_bounds__(256, 2) void gemm128_kernel(
    const float* __restrict__ A, const float* __restrict__ W,
    const float* __restrict__ bias, float* __restrict__ C,
    int M, int N, int K, int lda, int relu)
{
    __shared__ float As[16][128];
    __shared__ float Bs[16][128];
    int tid = threadIdx.x;
    int tx = tid & 15, ty = tid >> 4;
    int m0 = blockIdx.x * 128, n0 = blockIdx.y * 128;
    int arow = tid >> 1, acol = (tid & 1) * 8;
    int bk = tid >> 4, bc = (tid & 15) * 8;

    unsigned long long acc[8][4];
#pragma unroll
    for (int i = 0; i < 8; i++)
#pragma unroll
        for (int j = 0; j < 4; j++) acc[i][j] = 0ull;

    for (int kk = 0; kk < K; kk += 16) {
        float4 a0 = make_float4(0.f, 0.f, 0.f, 0.f), a1 = a0;
        if (m0 + arow < M) {
            const float* ap = &A[(size_t)(m0 + arow) * lda + kk + acol];
            a0 = *(const float4*)ap;
            a1 = *(const float4*)(ap + 4);
        }
        As[acol + 0][arow] = a0.x; As[acol + 1][arow] = a0.y;
        As[acol + 2][arow] = a0.z; As[acol + 3][arow] = a0.w;
        As[acol + 4][arow] = a1.x; As[acol + 5][arow] = a1.y;
        As[acol + 6][arow] = a1.z; As[acol + 7][arow] = a1.w;

        const float* wp = &W[(size_t)(kk + bk) * N + n0 + bc];
        *(float4*)&Bs[bk][bc]     = *(const float4*)wp;
        *(float4*)&Bs[bk][bc + 4] = *(const float4*)(wp + 4);
        __syncthreads();

#pragma unroll
        for (int k = 0; k < 16; k++) {
            float4 af0 = *(const float4*)&As[k][ty * 8];
            float4 af1 = *(const float4*)&As[k][ty * 8 + 4];
            ulonglong2 bb0 = *(const ulonglong2*)&Bs[k][tx * 8];
            ulonglong2 bb1 = *(const ulonglong2*)&Bs[k][tx * 8 + 4];
            unsigned long long bv[4] = {bb0.x, bb0.y, bb1.x, bb1.y};
            float av[8] = {af0.x, af0.y, af0.z, af0.w, af1.x, af1.y, af1.z, af1.w};
#pragma unroll
            for (int i = 0; i < 8; i++) {
                unsigned long long aa = bcast2(av[i]);
#pragma unroll
                for (int j = 0; j < 4; j++) fma2(acc[i][j], aa, bv[j]);
            }
        }
        __syncthreads();
    }

    float4 bv0 = *(const float4*)&bias[n0 + tx * 8];
    float4 bv1 = *(const float4*)&bias[n0 + tx * 8 + 4];
    float bb[8] = {bv0.x, bv0.y, bv0.z, bv0.w, bv1.x, bv1.y, bv1.z, bv1.w};
#pragma unroll
    for (int i = 0; i < 8; i++) {
        int r = m0 + ty * 8 + i;
        if (r < M) {
            float o[8];
#pragma unroll
            for (int j = 0; j < 4; j++) {
                float2 p = unpack2(acc[i][j]);
                o[j * 2]     = p.x + bb[j * 2];
                o[j * 2 + 1] = p.y + bb[j * 2 + 1];
            }
            if (relu) {
#pragma unroll
                for (int j = 0; j < 8; j++) o[j] = fmaxf(o[j], 0.f);
            }
            float* cp = &C[(size_t)r * N + n0 + tx * 8];
            *(float4*)cp       = make_float4(o[0], o[1], o[2], o[3]);
            *(float4*)(cp + 4) = make_float4(o[4], o[5], o[6], o[7]);
        }
    }
}

// ---- fused 7-way projection GEMM: all read A=x, N=K=128 -------------------
struct MultiArgs {
    const float* W[7];
    const float* Bv[7];
    float* C[7];
};

__global__ __launch_bounds__(256, 2) void gemm128_multi_kernel(
    const float* __restrict__ A, MultiArgs args, int M)
{
    __shared__ float As[16][128];
    __shared__ float Bs[16][128];
    const float* __restrict__ W = args.W[blockIdx.y];
    const float* __restrict__ bias = args.Bv[blockIdx.y];
    float* __restrict__ C = args.C[blockIdx.y];
    int tid = threadIdx.x;
    int tx = tid & 15, ty = tid >> 4;
    int m0 = blockIdx.x * 128;
    int arow = tid >> 1, acol = (tid & 1) * 8;
    int bk = tid >> 4, bc = (tid & 15) * 8;

    unsigned long long acc[8][4];
#pragma unroll
    for (int i = 0; i < 8; i++)
#pragma unroll
        for (int j = 0; j < 4; j++) acc[i][j] = 0ull;

    for (int kk = 0; kk < 128; kk += 16) {
        float4 a0 = make_float4(0.f, 0.f, 0.f, 0.f), a1 = a0;
        if (m0 + arow < M) {
            const float* ap = &A[(size_t)(m0 + arow) * 128 + kk + acol];
            a0 = *(const float4*)ap;
            a1 = *(const float4*)(ap + 4);
        }
        As[acol + 0][arow] = a0.x; As[acol + 1][arow] = a0.y;
        As[acol + 2][arow] = a0.z; As[acol + 3][arow] = a0.w;
        As[acol + 4][arow] = a1.x; As[acol + 5][arow] = a1.y;
        As[acol + 6][arow] = a1.z; As[acol + 7][arow] = a1.w;

        const float* wp = &W[(size_t)(kk + bk) * 128 + bc];
        *(float4*)&Bs[bk][bc]     = *(const float4*)wp;
        *(float4*)&Bs[bk][bc + 4] = *(const float4*)(wp + 4);
        __syncthreads();

#pragma unroll
        for (int k = 0; k < 16; k++) {
            float4 af0 = *(const float4*)&As[k][ty * 8];
            float4 af1 = *(const float4*)&As[k][ty * 8 + 4];
            ulonglong2 bb0 = *(const ulonglong2*)&Bs[k][tx * 8];
            ulonglong2 bb1 = *(const ulonglong2*)&Bs[k][tx * 8 + 4];
            unsigned long long bv[4] = {bb0.x, bb0.y, bb1.x, bb1.y};
            float av[8] = {af0.x, af0.y, af0.z, af0.w, af1.x, af1.y, af1.z, af1.w};
#pragma unroll
            for (int i = 0; i < 8; i++) {
                unsigned long long aa = bcast2(av[i]);
#pragma unroll
                for (int j = 0; j < 4; j++) fma2(acc[i][j], aa, bv[j]);
            }
        }
        __syncthreads();
    }

    float4 bv0 = *(const float4*)&bias[tx * 8];
    float4 bv1 = *(const float4*)&bias[tx * 8 + 4];
    float bb[8] = {bv0.x, bv0.y, bv0.z, bv0.w, bv1.x, bv1.y, bv1.z, bv1.w};
#pragma unroll
    for (int i = 0; i < 8; i++) {
        int r = m0 + ty * 8 + i;
        if (r < M) {
            float o[8];
#pragma unroll
            for (int j = 0; j < 4; j++) {
                float2 p = unpack2(acc[i][j]);
                o[j * 2]     = p.x + bb[j * 2];
                o[j * 2 + 1] = p.y + bb[j * 2 + 1];
            }
            float* cp = &C[(size_t)r * 128 + tx * 8];
            *(float4*)cp       = make_float4(o[0], o[1], o[2], o[3]);
            *(float4*)(cp + 4) = make_float4(o[4], o[5], o[6], o[7]);
        }
    }
}

// ---------------- LayerNorm family (128 threads = one row) ----------------
__device__ __forceinline__ float block_sum_128(float v, float* sb) {
#pragma unroll
    for (int o = 16; o; o >>= 1) v += __shfl_xor_sync(0xffffffffu, v, o);
    if ((threadIdx.x & 31) == 0) sb[threadIdx.x >> 5] = v;
    __syncthreads();
    float r = sb[0] + sb[1] + sb[2] + sb[3];
    __syncthreads();
    return r;
}

__global__ void ln_kernel(const float* __restrict__ in, const float* __restrict__ g,
                          const float* __restrict__ b, float* __restrict__ outp)
{
    __shared__ float sb[4];
    int t = threadIdx.x;
    size_t i = (size_t)blockIdx.x * 128 + t;
    float v = in[i];
    float mean = block_sum_128(v, sb) * (1.f / 128.f);
    float d = v - mean;
    float var = block_sum_128(d * d, sb) * (1.f / 128.f);
    outp[i] = d * rsqrtf(var + 1e-5f) * g[t] + b[t];
}

__global__ void lnsum4_kernel(const float* __restrict__ x, const float* __restrict__ a,
                              const float* __restrict__ bp, const float* __restrict__ c,
                              const float* __restrict__ g, const float* __restrict__ be,
                              float* __restrict__ outp)
{
    __shared__ float sb[4];
    int t = threadIdx.x;
    size_t i = (size_t)blockIdx.x * 128 + t;
    float v = x[i] + a[i] + bp[i] + c[i];
    float mean = block_sum_128(v, sb) * (1.f / 128.f);
    float d = v - mean;
    float var = block_sum_128(d * d, sb) * (1.f / 128.f);
    outp[i] = d * rsqrtf(var + 1e-5f) * g[t] + be[t];
}

// ln over (f1+f2+s), write attn2 and spin = attn2 * senx[row%N]
__global__ void ln2mul_kernel(const float* __restrict__ f1, const float* __restrict__ f2,
                              const float* __restrict__ s, const float* __restrict__ senx,
                              const float* __restrict__ g, const float* __restrict__ be,
                              float* __restrict__ attn2, float* __restrict__ spin)
{
    __shared__ float sb[4];
    int t = threadIdx.x;
    int r = blockIdx.x;
    size_t i = (size_t)r * 128 + t;
    float v = f1[i] + f2[i] + s[i];
    float mean = block_sum_128(v, sb) * (1.f / 128.f);
    float d = v - mean;
    float var = block_sum_128(d * d, sb) * (1.f / 128.f);
    float o = d * rsqrtf(var + 1e-5f) * g[t] + be[t];
    attn2[i] = o;
    spin[i]  = o * senx[(size_t)(r % NNODE) * 128 + t];
}

// out = attn2 + LN(f1+f2)
__global__ void final_kernel(const float* __restrict__ f1, const float* __restrict__ f2,
                             const float* __restrict__ attn2,
                             const float* __restrict__ g, const float* __restrict__ be,
                             float* __restrict__ outp)
{
    __shared__ float sb[4];
    int t = threadIdx.x;
    size_t i = (size_t)blockIdx.x * 128 + t;
    float v = f1[i] + f2[i];
    float mean = block_sum_128(v, sb) * (1.f / 128.f);
    float d = v - mean;
    float var = block_sum_128(d * d, sb) * (1.f / 128.f);
    float sp = d * rsqrtf(var + 1e-5f) * g[t] + be[t];
    outp[i] = attn2[i] + sp;
}

// ---------------- adaptive avg pool over node axis -------------------------
__global__ void pool_kernel(const float* __restrict__ Kin, const float* __restrict__ Vin,
                            float* __restrict__ Kp, float* __restrict__ Vp)
{
    int bt = blockIdx.x, c = blockIdx.y, d = threadIdx.x;
    int s = (c * NNODE) / CC;
    int e = ((c + 1) * NNODE + CC - 1) / CC;
    float inv = 1.f / (float)(e - s);
    float ak = 0.f, av = 0.f;
    for (int n = s; n < e; n++) {
        ak += Kin[((size_t)bt * NNODE + n) * DD + d];
        av += Vin[((size_t)bt * NNODE + n) * DD + d];
    }
    Kp[((size_t)bt * CC + c) * DD + d] = ak * inv;
    Vp[((size_t)bt * CC + c) * DD + d] = av * inv;
}

// ---------------- dtw attention: 400 keys, block = (bt, head) --------------
__global__ __launch_bounds__(256) void attn_dtw_kernel(
    const float* __restrict__ Q, const float* __restrict__ K,
    const float* __restrict__ V, float* __restrict__ O)
{
    extern __shared__ float sm[];
    float* Qs = sm;               // 400*16
    float* Kt = sm + 6400;        // 16*416
    float* Vt = sm + 6400 + 6656;
    int bt = blockIdx.x, h = blockIdx.y;
    size_t base = ((size_t)bt * NNODE) * DD + h * HDIM;
    int tid = threadIdx.x;
    for (int e = tid; e < NNODE * 4; e += 256) {
        int q = e >> 2, d4 = (e & 3) << 2;
        float4 qv = *(const float4*)&Q[base + (size_t)q * DD + d4];
        float4 kv = *(const float4*)&K[base + (size_t)q * DD + d4];
        float4 vv = *(const float4*)&V[base + (size_t)q * DD + d4];
        *(float4*)&Qs[q * 16 + d4] = qv;
        Kt[(d4 + 0) * 416 + q] = kv.x; Kt[(d4 + 1) * 416 + q] = kv.y;
        Kt[(d4 + 2) * 416 + q] = kv.z; Kt[(d4 + 3) * 416 + q] = kv.w;
        Vt[(d4 + 0) * 416 + q] = vv.x; Vt[(d4 + 1) * 416 + q] = vv.y;
        Vt[(d4 + 2) * 416 + q] = vv.z; Vt[(d4 + 3) * 416 + q] = vv.w;
    }
    __syncthreads();
    int warp = tid >> 5, lane = tid & 31;
    for (int pp = warp; pp < NNODE / 2; pp += 8) {
        int qa = pp * 2;
        float qva[16], qvb[16];
#pragma unroll
        for (int d = 0; d < 16; d++) {
            qva[d] = Qs[qa * 16 + d];
            qvb[d] = Qs[qa * 16 + 16 + d];
        }
        float sa[13], sbv[13];
        float mxa = -1e30f, mxb = -1e30f;
#pragma unroll
        for (int i = 0; i < 13; i++) {
            int j = lane + (i << 5);
            float s0 = -1e30f, s1 = -1e30f;
            if (j < NNODE) {
                s0 = 0.f; s1 = 0.f;
#pragma unroll
                for (int d = 0; d < 16; d++) {
                    float kv = Kt[d * 416 + j];
                    s0 = fmaf(qva[d], kv, s0);
                    s1 = fmaf(qvb[d], kv, s1);
                }
                s0 *= 0.25f; s1 *= 0.25f;
            }
            sa[i] = s0; sbv[i] = s1;
            mxa = fmaxf(mxa, s0); mxb = fmaxf(mxb, s1);
        }
#pragma unroll
        for (int o = 16; o; o >>= 1) {
            mxa = fmaxf(mxa, __shfl_xor_sync(0xffffffffu, mxa, o));
            mxb = fmaxf(mxb, __shfl_xor_sync(0xffffffffu, mxb, o));
        }
        float la = 0.f, lb = 0.f;
#pragma unroll
        for (int i = 0; i < 13; i++) {
            int j = lane + (i << 5);
            float pa = (j < NNODE) ? __expf(sa[i] - mxa) : 0.f;
            float pb = (j < NNODE) ? __expf(sbv[i] - mxb) : 0.f;
            sa[i] = pa; sbv[i] = pb;
            la += pa; lb += pb;
        }
#pragma unroll
        for (int o = 16; o; o >>= 1) {
            la += __shfl_xor_sync(0xffffffffu, la, o);
            lb += __shfl_xor_sync(0xffffffffu, lb, o);
        }
        float acca[16], accb[16];
#pragma unroll
        for (int d = 0; d < 16; d++) { acca[d] = 0.f; accb[d] = 0.f; }
#pragma unroll
        for (int i = 0; i < 13; i++) {
            int j = lane + (i << 5);
            if (j < NNODE) {
                float pa = sa[i], pb = sbv[i];
#pragma unroll
                for (int d = 0; d < 16; d++) {
                    float vv = Vt[d * 416 + j];
                    acca[d] = fmaf(pa, vv, acca[d]);
                    accb[d] = fmaf(pb, vv, accb[d]);
                }
            }
        }
#pragma unroll
        for (int d = 0; d < 16; d++) {
#pragma unroll
            for (int o = 16; o; o >>= 1) {
                acca[d] += __shfl_xor_sync(0xffffffffu, acca[d], o);
                accb[d] += __shfl_xor_sync(0xffffffffu, accb[d], o);
            }
        }
        if (lane < 16) {
            O[base + (size_t)qa * DD + lane]       = acca[lane] / la;
            O[base + (size_t)(qa + 1) * DD + lane] = accb[lane] / lb;
        }
    }
}

// ---------------- pooled attention: 64 keys + positional bias --------------
__global__ __launch_bounds__(256) void attn_adp_kernel(
    const float* __restrict__ Q, const float* __restrict__ Kp,
    const float* __restrict__ Vp, const float* __restrict__ pos,
    float* __restrict__ O)
{
    __shared__ float Qs[NNODE * 16];
    __shared__ float Kt[16 * 64];
    __shared__ float Vt[16 * 64];
    int bt = blockIdx.x, h = blockIdx.y, tid = threadIdx.x;
    size_t qbase = ((size_t)bt * NNODE) * DD + h * HDIM;
    size_t kbase = ((size_t)bt * CC) * DD + h * HDIM;
    for (int e = tid; e < NNODE * 4; e += 256) {
        int q = e >> 2, d4 = (e & 3) << 2;
        *(float4*)&Qs[q * 16 + d4] = *(const float4*)&Q[qbase + (size_t)q * DD + d4];
    }
    {
        int c = tid >> 2, d4 = (tid & 3) << 2;
        float4 kv = *(const float4*)&Kp[kbase + (size_t)c * DD + d4];
        float4 vv = *(const float4*)&Vp[kbase + (size_t)c * DD + d4];
        Kt[(d4 + 0) * 64 + c] = kv.x; Kt[(d4 + 1) * 64 + c] = kv.y;
        Kt[(d4 + 2) * 64 + c] = kv.z; Kt[(d4 + 3) * 64 + c] = kv.w;
        Vt[(d4 + 0) * 64 + c] = vv.x; Vt[(d4 + 1) * 64 + c] = vv.y;
        Vt[(d4 + 2) * 64 + c] = vv.z; Vt[(d4 + 3) * 64 + c] = vv.w;
    }
    __syncthreads();
    int warp = tid >> 5, lane = tid & 31;
    for (int pp = warp; pp < NNODE / 2; pp += 8) {
        int qa = pp * 2;
        float qva[16], qvb[16];
#pragma unroll
        for (int d = 0; d < 16; d++) {
            qva[d] = Qs[qa * 16 + d];
            qvb[d] = Qs[qa * 16 + 16 + d];
        }
        float s00 = 0.f, s01 = 0.f, s10 = 0.f, s11 = 0.f;
#pragma unroll
        for (int d = 0; d < 16; d++) {
            float k0 = Kt[d * 64 + lane], k1 = Kt[d * 64 + lane + 32];
            s00 = fmaf(qva[d], k0, s00); s01 = fmaf(qva[d], k1, s01);
            s10 = fmaf(qvb[d], k0, s10); s11 = fmaf(qvb[d], k1, s11);
        }
        s00 = s00 * 0.25f + pos[(size_t)qa * 64 + lane];
        s01 = s01 * 0.25f + pos[(size_t)qa * 64 + lane + 32];
        s10 = s10 * 0.25f + pos[(size_t)(qa + 1) * 64 + lane];
        s11 = s11 * 0.25f + pos[(size_t)(qa + 1) * 64 + lane + 32];
        float mxa = fmaxf(s00, s01), mxb = fmaxf(s10, s11);
#pragma unroll
        for (int o = 16; o; o >>= 1) {
            mxa = fmaxf(mxa, __shfl_xor_sync(0xffffffffu, mxa, o));
            mxb = fmaxf(mxb, __shfl_xor_sync(0xffffffffu, mxb, o));
        }
        float p00 = __expf(s00 - mxa), p01 = __expf(s01 - mxa);
        float p10 = __expf(s10 - mxb), p11 = __expf(s11 - mxb);
        float la = p00 + p01, lb = p10 + p11;
#pragma unroll
        for (int o = 16; o; o >>= 1) {
            la += __shfl_xor_sync(0xffffffffu, la, o);
            lb += __shfl_xor_sync(0xffffffffu, lb, o);
        }
        float acca[16], accb[16];
#pragma unroll
        for (int d = 0; d < 16; d++) {
            float v0 = Vt[d * 64 + lane], v1 = Vt[d * 64 + lane + 32];
            acca[d] = p00 * v0 + p01 * v1;
            accb[d] = p10 * v0 + p11 * v1;
        }
#pragma unroll
        for (int d = 0; d < 16; d++) {
#pragma unroll
            for (int o = 16; o; o >>= 1) {
                acca[d] += __shfl_xor_sync(0xffffffffu, acca[d], o);
                accb[d] += __shfl_xor_sync(0xffffffffu, accb[d], o);
            }
        }
        if (lane < 16) {
            O[qbase + (size_t)qa * DD + lane]       = acca[lane] / la;
            O[qbase + (size_t)(qa + 1) * DD + lane] = accb[lane] / lb;
        }
    }
}

// ---------------- GEANet edge path (sen -> sen_extra) ----------------------
__global__ void edge_kernel(const float* __restrict__ elin, const float* __restrict__ ew,
                            const float* __restrict__ eb, float* __restrict__ senx,
                            float* __restrict__ outtail)
{
    __shared__ float s0[128], s1[128], s2[128];
    int n = blockIdx.x, t = threadIdx.x;
    int h = t >> 4, u = t & 15;
    s0[t] = elin[(size_t)n * 128 + t];
    __syncthreads();
    float acc = eb[u];
#pragma unroll
    for (int k = 0; k < 16; k++) acc = fmaf(s0[k * 8 + h], ew[k * 16 + u], acc);
    s1[t] = acc;
    __syncthreads();
    float mx = -1e30f;
#pragma unroll
    for (int hh = 0; hh < 8; hh++) mx = fmaxf(mx, s1[hh * 16 + u]);
    float sume = 0.f;
#pragma unroll
    for (int hh = 0; hh < 8; hh++) sume += __expf(s1[hh * 16 + u] - mx);
    float a = __expf(acc - mx) / sume;
    s2[t] = a;
    __syncthreads();
    float rs = 0.f;
#pragma unroll
    for (int uu = 0; uu < 16; uu++) rs += s2[h * 16 + uu];
    float a2 = a / rs;
    __syncthreads();
    s0[t] = a2;
    __syncthreads();
    float y = eb[16 + u];
#pragma unroll
    for (int k = 0; k < 16; k++) y = fmaf(s0[h * 16 + k], ew[256 + k * 16 + u], y);
    senx[(size_t)n * 128 + t] = y;
    outtail[(size_t)n * 128 + t] = y;
}

// ---------------- GEANet node path (reshape-of-transpose perm) -------------
__global__ void node_kernel(const float* __restrict__ share, const float* __restrict__ nw,
                            const float* __restrict__ nb, float* __restrict__ extra)
{
    __shared__ float s0[128], s1[128], s2[128];
    int row = blockIdx.x;
    int b = row / (TT * NNODE), p = row % (TT * NNODE);
    int nn = p / TT, ll = p % TT;
    int t = threadIdx.x;
    int h = t >> 4, u = t & 15;
    s0[t] = share[(((size_t)b * TT + ll) * NNODE + nn) * 128 + t];
    __syncthreads();
    float acc = nb[u];
#pragma unroll
    for (int k = 0; k < 16; k++) acc = fmaf(s0[h * 16 + k], nw[k * 16 + u], acc);
    s1[t] = acc;
    __syncthreads();
    float mx = -1e30f;
#pragma unroll
    for (int hh = 0; hh < 8; hh++) mx = fmaxf(mx, s1[hh * 16 + u]);
    float sume = 0.f;
#pragma unroll
    for (int hh = 0; hh < 8; hh++) sume += __expf(s1[hh * 16 + u] - mx);
    float a = __expf(acc - mx) / sume;
    s2[t] = a;
    __syncthreads();
    float rs = 0.f;
#pragma unroll
    for (int uu = 0; uu < 16; uu++) rs += s2[h * 16 + uu];
    float a2 = a / rs;
    __syncthreads();
    s0[t] = a2;
    __syncthreads();
    float y = nb[16 + u];
#pragma unroll
    for (int k = 0; k < 16; k++) y = fmaf(s0[h * 16 + k], nw[256 + k * 16 + u], y);
    extra[(size_t)row * 128 + t] = y;
}

// ---------------- host orchestration ---------------------------------------
extern "C" void kernel_launch(void* const* d_in, const int* in_sizes, int n_in,
                              void* d_out, int out_size)
{
    const float* x         = (const float*)d_in[0];
    const float* spe       = (const float*)d_in[1];
    const float* dtw_qkv_w = (const float*)d_in[2];
    const float* dtw_qkv_b = (const float*)d_in[3];
    const float* dtw_out_w = (const float*)d_in[4];
    const float* dtw_out_b = (const float*)d_in[5];
    const float* att_qkv_w = (const float*)d_in[6];
    const float* att_qkv_b = (const float*)d_in[7];
    const float* att_out_w = (const float*)d_in[8];
    const float* att_out_b = (const float*)d_in[9];
    const float* adp_pos   = (const float*)d_in[10];
    const float* share_w   = (const float*)d_in[11];
    const float* share_b   = (const float*)d_in[12];
    const float* node_w    = (const float*)d_in[13];
    const float* node_b    = (const float*)d_in[14];
    const float* edge_w    = (const float*)d_in[15];
    const float* edge_b    = (const float*)d_in[16];
    const float* spatial_w = (const float*)d_in[17];
    const float* spatial_b = (const float*)d_in[18];
    const float* ff1w1     = (const float*)d_in[19];
    const float* ff1b1     = (const float*)d_in[20];
    const float* ff1w2     = (const float*)d_in[21];
    const float* ff1b2     = (const float*)d_in[22];
    const float* ff2w1     = (const float*)d_in[23];
    const float* ff2b1     = (const float*)d_in[24];
    const float* ff2w2     = (const float*)d_in[25];
    const float* ff2b2     = (const float*)d_in[26];
    const float* lns       = (const float*)d_in[27];
    const float* lnb       = (const float*)d_in[28];
    float* out = (float*)d_out;

    float* g = nullptr;
    { void* p; cudaGetSymbolAddress(&p, g_scratch); g = (float*)p; }
    float* zb = nullptr;
    { void* p; cudaGetSymbolAddress(&p, g_zerobias); zb = (float*)p; }
    float* Q1   = g + 0u * CHSZ;
    float* K1   = g + 1u * CHSZ;
    float* V1   = g + 2u * CHSZ;
    float* Q2   = g + 3u * CHSZ;
    float* K2   = g + 4u * CHSZ;
    float* V2   = g + 5u * CHSZ;
    float* SHR  = g + 6u * CHSZ;
    float* DTW  = g + 7u * CHSZ;
    float* OA   = g + 8u * CHSZ;
    float* B1   = g + 9u * CHSZ;
    float* B2   = g + 10u * CHSZ;
    float* B3   = g + 11u * CHSZ;
    float* B4   = g + 12u * CHSZ;
    float* HID  = g + OFF_HID;
    float* KP   = g + OFF_KP;
    float* VP   = g + OFF_VP;
    float* SEN  = g + OFF_SEN;
    float* ELIN = g + OFF_ELIN;
    float* SENX = g + OFF_SENX;
    float* T400 = g + OFF_T400;

    cudaFuncSetAttribute(attn_dtw_kernel,
                         cudaFuncAttributeMaxDynamicSharedMemorySize, 78848);

#define GEMM(A_, W_, Bi_, C_, M_, N_, K_, LDA_, R_) \
    gemm128_kernel<<<dim3(((M_) + 127) / 128, (N_) / 128), 256>>>(A_, W_, Bi_, C_, M_, N_, K_, LDA_, R_)

    // sen path
    GEMM(spe, spatial_w, spatial_b, T400, NNODE, DD, DD, DD, 0);
    ln_kernel<<<NNODE, 128>>>(T400, lns + 3 * 128, lnb + 3 * 128, SEN);
    GEMM(SEN, share_w, share_b, ELIN, NNODE, DD, DD, DD, 0);
    edge_kernel<<<NNODE, 128>>>(ELIN, edge_w, edge_b, SENX, out + (size_t)MROWS * DD);

    // fused QKV projections + GEANet share (all read x)
    {
        MultiArgs ma;
        ma.W[0] = dtw_qkv_w + 0 * DD * DD; ma.Bv[0] = dtw_qkv_b + 0 * DD; ma.C[0] = Q1;
        ma.W[1] = dtw_qkv_w + 1 * DD * DD; ma.Bv[1] = dtw_qkv_b + 1 * DD; ma.C[1] = K1;
        ma.W[2] = dtw_qkv_w + 2 * DD * DD; ma.Bv[2] = dtw_qkv_b + 2 * DD; ma.C[2] = V1;
        ma.W[3] = att_qkv_w + 0 * DD * DD; ma.Bv[3] = att_qkv_b + 0 * DD; ma.C[3] = Q2;
        ma.W[4] = att_qkv_w + 1 * DD * DD; ma.Bv[4] = att_qkv_b + 1 * DD; ma.C[4] = K2;
        ma.W[5] = att_qkv_w + 2 * DD * DD; ma.Bv[5] = att_qkv_b + 2 * DD; ma.C[5] = V2;
        ma.W[6] = share_w;                 ma.Bv[6] = share_b;            ma.C[6] = SHR;
        gemm128_multi_kernel<<<dim3(MROWS / 128, 7), 256>>>(x, ma, MROWS);
    }

    // GEANet node path
    node_kernel<<<MROWS, 128>>>(SHR, node_w, node_b, B1);

    // dtw attention + out projection
    attn_dtw_kernel<<<dim3(BTN, HH), 256, 78848>>>(Q1, K1, V1, B2);
    GEMM(B2, dtw_out_w, dtw_out_b, DTW, MROWS, DD, DD, DD, 0);

    // pooled attention + out projection
    pool_kernel<<<dim3(BTN, CC), 128>>>(K2, V2, KP, VP);
    attn_adp_kernel<<<dim3(BTN, HH), 256>>>(Q2, KP, VP, adp_pos, B2);
    GEMM(B2, att_out_w, att_out_b, OA, MROWS, DD, DD, DD, 0);

    // ln1 of (x + oa + dtw + extra)
    lnsum4_kernel<<<MROWS, 128>>>(x, OA, DTW, B1, lns + 0, lnb + 0, B4);

    // feed_forward1 (split-K=2 on down-proj) + ln2 + sen_extra multiply
    GEMM(B4, ff1w1, ff1b1, HID, MROWS, FFD, DD, DD, 1);
    GEMM(HID,        ff1w2,             ff1b2, B1,  MROWS, DD, FFD / 2, FFD, 0);
    GEMM(HID + FFD/2, ff1w2 + (size_t)(FFD/2) * DD, zb, SHR, MROWS, DD, FFD / 2, FFD, 0);
    ln2mul_kernel<<<MROWS, 128>>>(B1, SHR, B4, SENX, lns + 128, lnb + 128, B2, B3);

    // feed_forward2 (split-K=2 on down-proj) + spatial_norm + residual
    GEMM(B3, ff2w1, ff2b1, HID, MROWS, FFD, DD, DD, 1);
    GEMM(HID,        ff2w2,             ff2b2, B4, MROWS, DD, FFD / 2, FFD, 0);
    GEMM(HID + FFD/2, ff2w2 + (size_t)(FFD/2) * DD, zb, Q1, MROWS, DD, FFD / 2, FFD, 0);
    final_kernel<<<MROWS, 128>>>(B4, Q1, B2, lns + 2 * 128, lnb + 2 * 128, out);
#undef GEMM
}

// round 4
// speedup vs baseline: 2.6252x; 1.7636x over previous
#include <cuda_runtime.h>
#include <cstdint>

#define BB 8
#define TT 12
#define NNODE 400
#define DD 128
#define HH 8
#define HDIM 16
#define UU 16
#define CC 64
#define FFD 2048
#define MROWS (BB*TT*NNODE)   /* 38400 */
#define BTN (BB*TT)           /* 96 */

// ---- single scratch arena (no allocations allowed) ----
#define CHSZ 4915200u         /* MROWS*DD */
#define OFF_HID   (13u*CHSZ)
#define OFF_KP    (OFF_HID + (size_t)MROWS*FFD)
#define OFF_VP    (OFF_KP + (size_t)BTN*CC*DD)
#define OFF_SEN   (OFF_VP + (size_t)BTN*CC*DD)
#define OFF_ELIN  (OFF_SEN + (size_t)NNODE*DD)
#define OFF_SENX  (OFF_ELIN + (size_t)NNODE*DD)
#define OFF_T400  (OFF_SENX + (size_t)NNODE*DD)
#define SCRATCH_TOTAL (OFF_T400 + (size_t)NNODE*DD)

__device__ float g_scratch[SCRATCH_TOTAL];
__device__ float g_zerobias[FFD];   // static zero-init

// ---------------- tf32 helpers ---------------------------------------------
__device__ __forceinline__ unsigned cvt_tf32(float v) {
    unsigned r;
    asm("cvt.rna.tf32.f32 %0, %1;" : "=r"(r) : "f"(v));
    return r;
}
__device__ __forceinline__ void mma_tf32(float& c0, float& c1, float& c2, float& c3,
                                         unsigned a0, unsigned a1, unsigned a2, unsigned a3,
                                         unsigned b0, unsigned b1) {
    asm("mma.sync.aligned.m16n8k8.row.col.f32.tf32.tf32.f32 "
        "{%0,%1,%2,%3}, {%4,%5,%6,%7}, {%8,%9}, {%0,%1,%2,%3};"
        : "+f"(c0), "+f"(c1), "+f"(c2), "+f"(c3)
        : "r"(a0), "r"(a1), "r"(a2), "r"(a3), "r"(b0), "r"(b1));
}

// ---------------- tf32 tensor-core GEMM ------------------------------------
// C[z] = act(A[:, k0+ (0..kchunk)] @ W[k0.., :] + bias(z==0))
// tile 128x128, 256 threads, 8 warps (2x4), warp tile 64x32
#define SMPAD 136
__global__ __launch_bounds__(256, 2) void gemm_tf32_kernel(
    const float* __restrict__ A, const float* __restrict__ W,
    const float* __restrict__ bias, float* __restrict__ C,
    int M, int N, int kchunk, int lda, size_t zstride, int relu)
{
    __shared__ unsigned As[16][SMPAD];
    __shared__ unsigned Bs[16][SMPAD];
    int tid = threadIdx.x;
    int warp = tid >> 5, lane = tid & 31;
    int g = lane >> 2, tg = lane & 3;
    int wm = warp >> 2, wn = warp & 3;            // 2 x 4
    int m0 = blockIdx.x * 128, n0 = blockIdx.y * 128;
    int k0 = blockIdx.z * kchunk;

    int arow = tid >> 1, acol = (tid & 1) * 8;    // A staging: 128 rows x 16 k
    int bk = tid >> 4, bc = (tid & 15) * 8;       // B staging: 16 k x 128 n

    float acc[4][4][4];
#pragma unroll
    for (int i = 0; i < 4; i++)
#pragma unroll
        for (int j = 0; j < 4; j++)
#pragma unroll
            for (int r = 0; r < 4; r++) acc[i][j][r] = 0.f;

    for (int kk = 0; kk < kchunk; kk += 16) {
        // stage A (transposed to k-major) with tf32 convert
        float a8[8];
        if (m0 + arow < M) {
            const float* ap = &A[(size_t)(m0 + arow) * lda + k0 + kk + acol];
            float4 v0 = *(const float4*)ap;
            float4 v1 = *(const float4*)(ap + 4);
            a8[0] = v0.x; a8[1] = v0.y; a8[2] = v0.z; a8[3] = v0.w;
            a8[4] = v1.x; a8[5] = v1.y; a8[6] = v1.z; a8[7] = v1.w;
        } else {
#pragma unroll
            for (int j = 0; j < 8; j++) a8[j] = 0.f;
        }
#pragma unroll
        for (int j = 0; j < 8; j++) As[acol + j][arow] = cvt_tf32(a8[j]);

        // stage B (already k-major) with tf32 convert
        {
            const float* wp = &W[(size_t)(k0 + kk + bk) * N + n0 + bc];
            float4 v0 = *(const float4*)wp;
            float4 v1 = *(const float4*)(wp + 4);
            Bs[bk][bc + 0] = cvt_tf32(v0.x); Bs[bk][bc + 1] = cvt_tf32(v0.y);
            Bs[bk][bc + 2] = cvt_tf32(v0.z); Bs[bk][bc + 3] = cvt_tf32(v0.w);
            Bs[bk][bc + 4] = cvt_tf32(v1.x); Bs[bk][bc + 5] = cvt_tf32(v1.y);
            Bs[bk][bc + 6] = cvt_tf32(v1.z); Bs[bk][bc + 7] = cvt_tf32(v1.w);
        }
        __syncthreads();

#pragma unroll
        for (int step = 0; step < 2; step++) {
            int ko = step * 8;
            unsigned af[4][4];
#pragma unroll
            for (int ma = 0; ma < 4; ma++) {
                int mr = wm * 64 + ma * 16 + g;
                af[ma][0] = As[ko + tg][mr];
                af[ma][1] = As[ko + tg][mr + 8];
                af[ma][2] = As[ko + tg + 4][mr];
                af[ma][3] = As[ko + tg + 4][mr + 8];
            }
            unsigned bf[4][2];
#pragma unroll
            for (int na = 0; na < 4; na++) {
                int nc = wn * 32 + na * 8 + g;
                bf[na][0] = Bs[ko + tg][nc];
                bf[na][1] = Bs[ko + tg + 4][nc];
            }
#pragma unroll
            for (int ma = 0; ma < 4; ma++)
#pragma unroll
                for (int na = 0; na < 4; na++)
                    mma_tf32(acc[ma][na][0], acc[ma][na][1], acc[ma][na][2], acc[ma][na][3],
                             af[ma][0], af[ma][1], af[ma][2], af[ma][3],
                             bf[na][0], bf[na][1]);
        }
        __syncthreads();
    }

    const float* bp = (blockIdx.z == 0) ? bias : g_zerobias;
    float* Cz = C + (size_t)blockIdx.z * zstride;
#pragma unroll
    for (int ma = 0; ma < 4; ma++) {
        int r0 = m0 + wm * 64 + ma * 16 + g;
        int r1 = r0 + 8;
#pragma unroll
        for (int na = 0; na < 4; na++) {
            int col = n0 + wn * 32 + na * 8 + tg * 2;
            float b0 = bp[col], b1 = bp[col + 1];
            float o0 = acc[ma][na][0] + b0, o1 = acc[ma][na][1] + b1;
            float o2 = acc[ma][na][2] + b0, o3 = acc[ma][na][3] + b1;
            if (relu) {
                o0 = fmaxf(o0, 0.f); o1 = fmaxf(o1, 0.f);
                o2 = fmaxf(o2, 0.f); o3 = fmaxf(o3, 0.f);
            }
            if (r0 < M) *(float2*)&Cz[(size_t)r0 * N + col] = make_float2(o0, o1);
            if (r1 < M) *(float2*)&Cz[(size_t)r1 * N + col] = make_float2(o2, o3);
        }
    }
}

// ---------------- LayerNorm family (128 threads = one row) ----------------
__device__ __forceinline__ float block_sum_128(float v, float* sb) {
#pragma unroll
    for (int o = 16; o; o >>= 1) v += __shfl_xor_sync(0xffffffffu, v, o);
    if ((threadIdx.x & 31) == 0) sb[threadIdx.x >> 5] = v;
    __syncthreads();
    float r = sb[0] + sb[1] + sb[2] + sb[3];
    __syncthreads();
    return r;
}

__global__ void ln_kernel(const float* __restrict__ in, const float* __restrict__ g,
                          const float* __restrict__ b, float* __restrict__ outp)
{
    __shared__ float sb[4];
    int t = threadIdx.x;
    size_t i = (size_t)blockIdx.x * 128 + t;
    float v = in[i];
    float mean = block_sum_128(v, sb) * (1.f / 128.f);
    float d = v - mean;
    float var = block_sum_128(d * d, sb) * (1.f / 128.f);
    outp[i] = d * rsqrtf(var + 1e-5f) * g[t] + b[t];
}

__global__ void lnsum4_kernel(const float* __restrict__ x, const float* __restrict__ a,
                              const float* __restrict__ bp, const float* __restrict__ c,
                              const float* __restrict__ g, const float* __restrict__ be,
                              float* __restrict__ outp)
{
    __shared__ float sb[4];
    int t = threadIdx.x;
    size_t i = (size_t)blockIdx.x * 128 + t;
    float v = x[i] + a[i] + bp[i] + c[i];
    float mean = block_sum_128(v, sb) * (1.f / 128.f);
    float d = v - mean;
    float var = block_sum_128(d * d, sb) * (1.f / 128.f);
    outp[i] = d * rsqrtf(var + 1e-5f) * g[t] + be[t];
}

// ln over (sum of 4 split-K partials + s); write attn2 and spin = attn2*senx
__global__ void ln2mul_kernel(const float* __restrict__ parts, const float* __restrict__ s,
                              const float* __restrict__ senx,
                              const float* __restrict__ g, const float* __restrict__ be,
                              float* __restrict__ attn2, float* __restrict__ spin)
{
    __shared__ float sb[4];
    int t = threadIdx.x;
    int r = blockIdx.x;
    size_t i = (size_t)r * 128 + t;
    float v = parts[i] + parts[i + (size_t)CHSZ] + parts[i + 2u * (size_t)CHSZ]
            + parts[i + 3u * (size_t)CHSZ] + s[i];
    float mean = block_sum_128(v, sb) * (1.f / 128.f);
    float d = v - mean;
    float var = block_sum_128(d * d, sb) * (1.f / 128.f);
    float o = d * rsqrtf(var + 1e-5f) * g[t] + be[t];
    attn2[i] = o;
    spin[i]  = o * senx[(size_t)(r % NNODE) * 128 + t];
}

// out = attn2 + LN(sum of 4 split-K partials)
__global__ void final_kernel(const float* __restrict__ parts, const float* __restrict__ attn2,
                             const float* __restrict__ g, const float* __restrict__ be,
                             float* __restrict__ outp)
{
    __shared__ float sb[4];
    int t = threadIdx.x;
    size_t i = (size_t)blockIdx.x * 128 + t;
    float v = parts[i] + parts[i + (size_t)CHSZ] + parts[i + 2u * (size_t)CHSZ]
            + parts[i + 3u * (size_t)CHSZ];
    float mean = block_sum_128(v, sb) * (1.f / 128.f);
    float d = v - mean;
    float var = block_sum_128(d * d, sb) * (1.f / 128.f);
    float sp = d * rsqrtf(var + 1e-5f) * g[t] + be[t];
    outp[i] = attn2[i] + sp;
}

// ---------------- adaptive avg pool over node axis -------------------------
__global__ void pool_kernel(const float* __restrict__ Kin, const float* __restrict__ Vin,
                            float* __restrict__ Kp, float* __restrict__ Vp)
{
    int bt = blockIdx.x, c = blockIdx.y, d = threadIdx.x;
    int s = (c * NNODE) / CC;
    int e = ((c + 1) * NNODE + CC - 1) / CC;
    float inv = 1.f / (float)(e - s);
    float ak = 0.f, av = 0.f;
    for (int n = s; n < e; n++) {
        ak += Kin[((size_t)bt * NNODE + n) * DD + d];
        av += Vin[((size_t)bt * NNODE + n) * DD + d];
    }
    Kp[((size_t)bt * CC + c) * DD + d] = ak * inv;
    Vp[((size_t)bt * CC + c) * DD + d] = av * inv;
}

// ---------------- dtw attention: 400 keys, block = (bt, head) --------------
__global__ __launch_bounds__(256) void attn_dtw_kernel(
    const float* __restrict__ Q, const float* __restrict__ K,
    const float* __restrict__ V, float* __restrict__ O)
{
    extern __shared__ float sm[];
    float* Qs = sm;               // 400*16
    float* Kt = sm + 6400;        // 16*416
    float* Vt = sm + 6400 + 6656;
    int bt = blockIdx.x, h = blockIdx.y;
    size_t base = ((size_t)bt * NNODE) * DD + h * HDIM;
    int tid = threadIdx.x;
    for (int e = tid; e < NNODE * 4; e += 256) {
        int q = e >> 2, d4 = (e & 3) << 2;
        float4 qv = *(const float4*)&Q[base + (size_t)q * DD + d4];
        float4 kv = *(const float4*)&K[base + (size_t)q * DD + d4];
        float4 vv = *(const float4*)&V[base + (size_t)q * DD + d4];
        *(float4*)&Qs[q * 16 + d4] = qv;
        Kt[(d4 + 0) * 416 + q] = kv.x; Kt[(d4 + 1) * 416 + q] = kv.y;
        Kt[(d4 + 2) * 416 + q] = kv.z; Kt[(d4 + 3) * 416 + q] = kv.w;
        Vt[(d4 + 0) * 416 + q] = vv.x; Vt[(d4 + 1) * 416 + q] = vv.y;
        Vt[(d4 + 2) * 416 + q] = vv.z; Vt[(d4 + 3) * 416 + q] = vv.w;
    }
    __syncthreads();
    int warp = tid >> 5, lane = tid & 31;
    for (int pp = warp; pp < NNODE / 2; pp += 8) {
        int qa = pp * 2;
        float qva[16], qvb[16];
#pragma unroll
        for (int d = 0; d < 16; d++) {
            qva[d] = Qs[qa * 16 + d];
            qvb[d] = Qs[qa * 16 + 16 + d];
        }
        float sa[13], sbv[13];
        float mxa = -1e30f, mxb = -1e30f;
#pragma unroll
        for (int i = 0; i < 13; i++) {
            int j = lane + (i << 5);
            float s0 = -1e30f, s1 = -1e30f;
            if (j < NNODE) {
                s0 = 0.f; s1 = 0.f;
#pragma unroll
                for (int d = 0; d < 16; d++) {
                    float kv = Kt[d * 416 + j];
                    s0 = fmaf(qva[d], kv, s0);
                    s1 = fmaf(qvb[d], kv, s1);
                }
                s0 *= 0.25f; s1 *= 0.25f;
            }
            sa[i] = s0; sbv[i] = s1;
            mxa = fmaxf(mxa, s0); mxb = fmaxf(mxb, s1);
        }
#pragma unroll
        for (int o = 16; o; o >>= 1) {
            mxa = fmaxf(mxa, __shfl_xor_sync(0xffffffffu, mxa, o));
            mxb = fmaxf(mxb, __shfl_xor_sync(0xffffffffu, mxb, o));
        }
        float la = 0.f, lb = 0.f;
#pragma unroll
        for (int i = 0; i < 13; i++) {
            int j = lane + (i << 5);
            float pa = (j < NNODE) ? __expf(sa[i] - mxa) : 0.f;
            float pb = (j < NNODE) ? __expf(sbv[i] - mxb) : 0.f;
            sa[i] = pa; sbv[i] = pb;
            la += pa; lb += pb;
        }
#pragma unroll
        for (int o = 16; o; o >>= 1) {
            la += __shfl_xor_sync(0xffffffffu, la, o);
            lb += __shfl_xor_sync(0xffffffffu, lb, o);
        }
        float acca[16], accb[16];
#pragma unroll
        for (int d = 0; d < 16; d++) { acca[d] = 0.f; accb[d] = 0.f; }
#pragma unroll
        for (int i = 0; i < 13; i++) {
            int j = lane + (i << 5);
            if (j < NNODE) {
                float pa = sa[i], pb = sbv[i];
#pragma unroll
                for (int d = 0; d < 16; d++) {
                    float vv = Vt[d * 416 + j];
                    acca[d] = fmaf(pa, vv, acca[d]);
                    accb[d] = fmaf(pb, vv, accb[d]);
                }
            }
        }
#pragma unroll
        for (int d = 0; d < 16; d++) {
#pragma unroll
            for (int o = 16; o; o >>= 1) {
                acca[d] += __shfl_xor_sync(0xffffffffu, acca[d], o);
                accb[d] += __shfl_xor_sync(0xffffffffu, accb[d], o);
            }
        }
        if (lane < 16) {
            O[base + (size_t)qa * DD + lane]       = acca[lane] / la;
            O[base + (size_t)(qa + 1) * DD + lane] = accb[lane] / lb;
        }
    }
}

// ---------------- pooled attention: 64 keys + positional bias --------------
__global__ __launch_bounds__(256) void attn_adp_kernel(
    const float* __restrict__ Q, const float* __restrict__ Kp,
    const float* __restrict__ Vp, const float* __restrict__ pos,
    float* __restrict__ O)
{
    __shared__ float Qs[NNODE * 16];
    __shared__ float Kt[16 * 64];
    __shared__ float Vt[16 * 64];
    int bt = blockIdx.x, h = blockIdx.y, tid = threadIdx.x;
    size_t qbase = ((size_t)bt * NNODE) * DD + h * HDIM;
    size_t kbase = ((size_t)bt * CC) * DD + h * HDIM;
    for (int e = tid; e < NNODE * 4; e += 256) {
        int q = e >> 2, d4 = (e & 3) << 2;
        *(float4*)&Qs[q * 16 + d4] = *(const float4*)&Q[qbase + (size_t)q * DD + d4];
    }
    {
        int c = tid >> 2, d4 = (tid & 3) << 2;
        float4 kv = *(const float4*)&Kp[kbase + (size_t)c * DD + d4];
        float4 vv = *(const float4*)&Vp[kbase + (size_t)c * DD + d4];
        Kt[(d4 + 0) * 64 + c] = kv.x; Kt[(d4 + 1) * 64 + c] = kv.y;
        Kt[(d4 + 2) * 64 + c] = kv.z; Kt[(d4 + 3) * 64 + c] = kv.w;
        Vt[(d4 + 0) * 64 + c] = vv.x; Vt[(d4 + 1) * 64 + c] = vv.y;
        Vt[(d4 + 2) * 64 + c] = vv.z; Vt[(d4 + 3) * 64 + c] = vv.w;
    }
    __syncthreads();
    int warp = tid >> 5, lane = tid & 31;
    for (int pp = warp; pp < NNODE / 2; pp += 8) {
        int qa = pp * 2;
        float qva[16], qvb[16];
#pragma unroll
        for (int d = 0; d < 16; d++) {
            qva[d] = Qs[qa * 16 + d];
            qvb[d] = Qs[qa * 16 + 16 + d];
        }
        float s00 = 0.f, s01 = 0.f, s10 = 0.f, s11 = 0.f;
#pragma unroll
        for (int d = 0; d < 16; d++) {
            float k0 = Kt[d * 64 + lane], k1 = Kt[d * 64 + lane + 32];
            s00 = fmaf(qva[d], k0, s00); s01 = fmaf(qva[d], k1, s01);
            s10 = fmaf(qvb[d], k0, s10); s11 = fmaf(qvb[d], k1, s11);
        }
        s00 = s00 * 0.25f + pos[(size_t)qa * 64 + lane];
        s01 = s01 * 0.25f + pos[(size_t)qa * 64 + lane + 32];
        s10 = s10 * 0.25f + pos[(size_t)(qa + 1) * 64 + lane];
        s11 = s11 * 0.25f + pos[(size_t)(qa + 1) * 64 + lane + 32];
        float mxa = fmaxf(s00, s01), mxb = fmaxf(s10, s11);
#pragma unroll
        for (int o = 16; o; o >>= 1) {
            mxa = fmaxf(mxa, __shfl_xor_sync(0xffffffffu, mxa, o));
            mxb = fmaxf(mxb, __shfl_xor_sync(0xffffffffu, mxb, o));
        }
        float p00 = __expf(s00 - mxa), p01 = __expf(s01 - mxa);
        float p10 = __expf(s10 - mxb), p11 = __expf(s11 - mxb);
        float la = p00 + p01, lb = p10 + p11;
#pragma unroll
        for (int o = 16; o; o >>= 1) {
            la += __shfl_xor_sync(0xffffffffu, la, o);
            lb += __shfl_xor_sync(0xffffffffu, lb, o);
        }
        float acca[16], accb[16];
#pragma unroll
        for (int d = 0; d < 16; d++) {
            float v0 = Vt[d * 64 + lane], v1 = Vt[d * 64 + lane + 32];
            acca[d] = p00 * v0 + p01 * v1;
            accb[d] = p10 * v0 + p11 * v1;
        }
#pragma unroll
        for (int d = 0; d < 16; d++) {
#pragma unroll
            for (int o = 16; o; o >>= 1) {
                acca[d] += __shfl_xor_sync(0xffffffffu, acca[d], o);
                accb[d] += __shfl_xor_sync(0xffffffffu, accb[d], o);
            }
        }
        if (lane < 16) {
            O[qbase + (size_t)qa * DD + lane]       = acca[lane] / la;
            O[qbase + (size_t)(qa + 1) * DD + lane] = accb[lane] / lb;
        }
    }
}

// ---------------- GEANet edge path (sen -> sen_extra) ----------------------
__global__ void edge_kernel(const float* __restrict__ elin, const float* __restrict__ ew,
                            const float* __restrict__ eb, float* __restrict__ senx,
                            float* __restrict__ outtail)
{
    __shared__ float s0[128], s1[128], s2[128];
    int n = blockIdx.x, t = threadIdx.x;
    int h = t >> 4, u = t & 15;
    s0[t] = elin[(size_t)n * 128 + t];
    __syncthreads();
    float acc = eb[u];
#pragma unroll
    for (int k = 0; k < 16; k++) acc = fmaf(s0[k * 8 + h], ew[k * 16 + u], acc);
    s1[t] = acc;
    __syncthreads();
    float mx = -1e30f;
#pragma unroll
    for (int hh = 0; hh < 8; hh++) mx = fmaxf(mx, s1[hh * 16 + u]);
    float sume = 0.f;
#pragma unroll
    for (int hh = 0; hh < 8; hh++) sume += __expf(s1[hh * 16 + u] - mx);
    float a = __expf(acc - mx) / sume;
    s2[t] = a;
    __syncthreads();
    float rs = 0.f;
#pragma unroll
    for (int uu = 0; uu < 16; uu++) rs += s2[h * 16 + uu];
    float a2 = a / rs;
    __syncthreads();
    s0[t] = a2;
    __syncthreads();
    float y = eb[16 + u];
#pragma unroll
    for (int k = 0; k < 16; k++) y = fmaf(s0[h * 16 + k], ew[256 + k * 16 + u], y);
    senx[(size_t)n * 128 + t] = y;
    outtail[(size_t)n * 128 + t] = y;
}

// ---------------- GEANet node path (reshape-of-transpose perm) -------------
__global__ void node_kernel(const float* __restrict__ share, const float* __restrict__ nw,
                            const float* __restrict__ nb, float* __restrict__ extra)
{
    __shared__ float s0[128], s1[128], s2[128];
    int row = blockIdx.x;
    int b = row / (TT * NNODE), p = row % (TT * NNODE);
    int nn = p / TT, ll = p % TT;
    int t = threadIdx.x;
    int h = t >> 4, u = t & 15;
    s0[t] = share[(((size_t)b * TT + ll) * NNODE + nn) * 128 + t];
    __syncthreads();
    float acc = nb[u];
#pragma unroll
    for (int k = 0; k < 16; k++) acc = fmaf(s0[h * 16 + k], nw[k * 16 + u], acc);
    s1[t] = acc;
    __syncthreads();
    float mx = -1e30f;
#pragma unroll
    for (int hh = 0; hh < 8; hh++) mx = fmaxf(mx, s1[hh * 16 + u]);
    float sume = 0.f;
#pragma unroll
    for (int hh = 0; hh < 8; hh++) sume += __expf(s1[hh * 16 + u] - mx);
    float a = __expf(acc - mx) / sume;
    s2[t] = a;
    __syncthreads();
    float rs = 0.f;
#pragma unroll
    for (int uu = 0; uu < 16; uu++) rs += s2[h * 16 + uu];
    float a2 = a / rs;
    __syncthreads();
    s0[t] = a2;
    __syncthreads();
    float y = nb[16 + u];
#pragma unroll
    for (int k = 0; k < 16; k++) y = fmaf(s0[h * 16 + k], nw[256 + k * 16 + u], y);
    extra[(size_t)row * 128 + t] = y;
}

// ---------------- host orchestration ---------------------------------------
extern "C" void kernel_launch(void* const* d_in, const int* in_sizes, int n_in,
                              void* d_out, int out_size)
{
    const float* x         = (const float*)d_in[0];
    const float* spe       = (const float*)d_in[1];
    const float* dtw_qkv_w = (const float*)d_in[2];
    const float* dtw_qkv_b = (const float*)d_in[3];
    const float* dtw_out_w = (const float*)d_in[4];
    const float* dtw_out_b = (const float*)d_in[5];
    const float* att_qkv_w = (const float*)d_in[6];
    const float* att_qkv_b = (const float*)d_in[7];
    const float* att_out_w = (const float*)d_in[8];
    const float* att_out_b = (const float*)d_in[9];
    const float* adp_pos   = (const float*)d_in[10];
    const float* share_w   = (const float*)d_in[11];
    const float* share_b   = (const float*)d_in[12];
    const float* node_w    = (const float*)d_in[13];
    const float* node_b    = (const float*)d_in[14];
    const float* edge_w    = (const float*)d_in[15];
    const float* edge_b    = (const float*)d_in[16];
    const float* spatial_w = (const float*)d_in[17];
    const float* spatial_b = (const float*)d_in[18];
    const float* ff1w1     = (const float*)d_in[19];
    const float* ff1b1     = (const float*)d_in[20];
    const float* ff1w2     = (const float*)d_in[21];
    const float* ff1b2     = (const float*)d_in[22];
    const float* ff2w1     = (const float*)d_in[23];
    const float* ff2b1     = (const float*)d_in[24];
    const float* ff2w2     = (const float*)d_in[25];
    const float* ff2b2     = (const float*)d_in[26];
    const float* lns       = (const float*)d_in[27];
    const float* lnb       = (const float*)d_in[28];
    float* out = (float*)d_out;

    float* g = nullptr;
    { void* p; cudaGetSymbolAddress(&p, g_scratch); g = (float*)p; }
    float* PART = g + 0u * CHSZ;           // 4 split-K partials (chunks 0-3)
    float* Q1   = g + 0u * CHSZ;
    float* K1   = g + 1u * CHSZ;
    float* V1   = g + 2u * CHSZ;
    float* Q2   = g + 3u * CHSZ;
    float* K2   = g + 4u * CHSZ;
    float* V2   = g + 5u * CHSZ;
    float* SHR  = g + 6u * CHSZ;
    float* DTW  = g + 7u * CHSZ;
    float* OA   = g + 8u * CHSZ;
    float* B1   = g + 9u * CHSZ;
    float* B2   = g + 10u * CHSZ;
    float* B3   = g + 11u * CHSZ;
    float* B4   = g + 12u * CHSZ;
    float* HID  = g + OFF_HID;
    float* KP   = g + OFF_KP;
    float* VP   = g + OFF_VP;
    float* SEN  = g + OFF_SEN;
    float* ELIN = g + OFF_ELIN;
    float* SENX = g + OFF_SENX;
    float* T400 = g + OFF_T400;

    cudaFuncSetAttribute(attn_dtw_kernel,
                         cudaFuncAttributeMaxDynamicSharedMemorySize, 78848);

#define GEMM(A_, W_, Bi_, C_, M_, N_, K_, LDA_, R_) \
    gemm_tf32_kernel<<<dim3(((M_) + 127) / 128, (N_) / 128, 1), 256>>>( \
        A_, W_, Bi_, C_, M_, N_, K_, LDA_, 0, R_)

    // sen path
    GEMM(spe, spatial_w, spatial_b, T400, NNODE, DD, DD, DD, 0);
    ln_kernel<<<NNODE, 128>>>(T400, lns + 3 * 128, lnb + 3 * 128, SEN);
    GEMM(SEN, share_w, share_b, ELIN, NNODE, DD, DD, DD, 0);
    edge_kernel<<<NNODE, 128>>>(ELIN, edge_w, edge_b, SENX, out + (size_t)MROWS * DD);

    // QKV projections + GEANet share (all read x)
    GEMM(x, dtw_qkv_w + 0 * DD * DD, dtw_qkv_b + 0 * DD, Q1, MROWS, DD, DD, DD, 0);
    GEMM(x, dtw_qkv_w + 1 * DD * DD, dtw_qkv_b + 1 * DD, K1, MROWS, DD, DD, DD, 0);
    GEMM(x, dtw_qkv_w + 2 * DD * DD, dtw_qkv_b + 2 * DD, V1, MROWS, DD, DD, DD, 0);
    GEMM(x, att_qkv_w + 0 * DD * DD, att_qkv_b + 0 * DD, Q2, MROWS, DD, DD, DD, 0);
    GEMM(x, att_qkv_w + 1 * DD * DD, att_qkv_b + 1 * DD, K2, MROWS, DD, DD, DD, 0);
    GEMM(x, att_qkv_w + 2 * DD * DD, att_qkv_b + 2 * DD, V2, MROWS, DD, DD, DD, 0);
    GEMM(x, share_w, share_b, SHR, MROWS, DD, DD, DD, 0);

    // GEANet node path
    node_kernel<<<MROWS, 128>>>(SHR, node_w, node_b, B1);

    // dtw attention + out projection
    attn_dtw_kernel<<<dim3(BTN, HH), 256, 78848>>>(Q1, K1, V1, B2);
    GEMM(B2, dtw_out_w, dtw_out_b, DTW, MROWS, DD, DD, DD, 0);

    // pooled attention + out projection
    pool_kernel<<<dim3(BTN, CC), 128>>>(K2, V2, KP, VP);
    attn_adp_kernel<<<dim3(BTN, HH), 256>>>(Q2, KP, VP, adp_pos, B2);
    GEMM(B2, att_out_w, att_out_b, OA, MROWS, DD, DD, DD, 0);

    // ln1 of (x + oa + dtw + extra)   [Q1/B2 now dead -> PART reuse legal]
    lnsum4_kernel<<<MROWS, 128>>>(x, OA, DTW, B1, lns + 0, lnb + 0, B4);

    // feed_forward1: up (relu) + split-K=4 down -> 4 partials; ln2 + senx mul
    GEMM(B4, ff1w1, ff1b1, HID, MROWS, FFD, DD, DD, 1);
    gemm_tf32_kernel<<<dim3(MROWS / 128, 1, 4), 256>>>(
        HID, ff1w2, ff1b2, PART, MROWS, DD, FFD / 4, FFD, (size_t)CHSZ, 0);
    ln2mul_kernel<<<MROWS, 128>>>(PART, B4, SENX, lns + 128, lnb + 128, B2, B3);

    // feed_forward2: up (relu) + split-K=4 down; spatial_norm + residual
    GEMM(B3, ff2w1, ff2b1, HID, MROWS, FFD, DD, DD, 1);
    gemm_tf32_kernel<<<dim3(MROWS / 128, 1, 4), 256>>>(
        HID, ff2w2, ff2b2, PART, MROWS, DD, FFD / 4, FFD, (size_t)CHSZ, 0);
    final_kernel<<<MROWS, 128>>>(PART, B2, lns + 2 * 128, lnb + 2 * 128, out);
#undef GEMM
}